// round 14
// baseline (speedup 1.0000x reference)
#include <cuda_runtime.h>
#include <cuda_fp16.h>
#include <cstdint>

// ---------------------------------------------------------------------------
// VideoAttentionModel  B=8, S=4096, D=256, fp32 in/out.
// Round 14: 16-warp flash. Warp pairs per 16 q-rows: S split by key-half,
// P exchanged via smem (fp16), PV split by d-half (oacc 64 regs) -> 512
// threads/CTA, 4 warps/SMSP for latency hiding.
// ---------------------------------------------------------------------------

#define NROWS 32768
#define NELEM (NROWS * 256)

// Scratch (device globals — allocation-free rule)
__device__ __half g_xh[NELEM];     // x fp16; later reused as fp16 logits
__device__ __half g_wt[4 * 256 * 256];
__device__ __half g_qh[NELEM];
__device__ __half g_kh[NELEM];
__device__ __half g_vh[NELEM];
__device__ __half g_ctxh[NELEM];
__device__ float  g_w[2 * NROWS];
__device__ float  g_wn[NROWS];

// ---------------------------------------------------------------------------
// PTX helpers (sm_80-era instructions only)
// ---------------------------------------------------------------------------
__device__ __forceinline__ uint32_t smem_u32(const void* p) {
    uint32_t a;
    asm("{ .reg .u64 t; cvta.to.shared.u64 t, %1; cvt.u32.u64 %0, t; }"
        : "=r"(a) : "l"(p));
    return a;
}
__device__ __forceinline__ uint32_t ex2h2(uint32_t x) {   // 2^x on f16x2
    uint32_t y; asm("ex2.approx.f16x2 %0, %1;" : "=r"(y) : "r"(x)); return y;
}
__device__ __forceinline__ void ldsm4(uint32_t &r0, uint32_t &r1, uint32_t &r2,
                                      uint32_t &r3, uint32_t a) {
    asm volatile("ldmatrix.sync.aligned.m8n8.x4.shared.b16 {%0,%1,%2,%3}, [%4];"
                 : "=r"(r0), "=r"(r1), "=r"(r2), "=r"(r3) : "r"(a));
}
__device__ __forceinline__ void ldsm4t(uint32_t &r0, uint32_t &r1, uint32_t &r2,
                                       uint32_t &r3, uint32_t a) {
    asm volatile("ldmatrix.sync.aligned.m8n8.x4.trans.shared.b16 {%0,%1,%2,%3}, [%4];"
                 : "=r"(r0), "=r"(r1), "=r"(r2), "=r"(r3) : "r"(a));
}
__device__ __forceinline__ void sts32(uint32_t a, uint32_t v) {
    asm volatile("st.shared.b32 [%0], %1;" :: "r"(a), "r"(v) : "memory");
}
// fp32-accumulate HMMA
__device__ __forceinline__ void mma16816(float (&c)[4], uint32_t a0, uint32_t a1,
                                         uint32_t a2, uint32_t a3,
                                         uint32_t b0, uint32_t b1) {
    asm volatile(
        "mma.sync.aligned.m16n8k16.row.col.f32.f16.f16.f32 "
        "{%0,%1,%2,%3}, {%4,%5,%6,%7}, {%8,%9}, {%0,%1,%2,%3};"
        : "+f"(c[0]), "+f"(c[1]), "+f"(c[2]), "+f"(c[3])
        : "r"(a0), "r"(a1), "r"(a2), "r"(a3), "r"(b0), "r"(b1));
}
// fp16-accumulate HMMA (scores only)
__device__ __forceinline__ void mma16816h(uint32_t &c0, uint32_t &c1,
                                          uint32_t a0, uint32_t a1,
                                          uint32_t a2, uint32_t a3,
                                          uint32_t b0, uint32_t b1) {
    asm volatile(
        "mma.sync.aligned.m16n8k16.row.col.f16.f16.f16.f16 "
        "{%0,%1}, {%2,%3,%4,%5}, {%6,%7}, {%0,%1};"
        : "+r"(c0), "+r"(c1)
        : "r"(a0), "r"(a1), "r"(a2), "r"(a3), "r"(b0), "r"(b1));
}

#define CP16(s, g) \
    asm volatile("cp.async.cg.shared.global [%0], [%1], 16;" :: "r"(s), "l"(g))
#define CP_COMMIT() asm volatile("cp.async.commit_group;" ::: "memory")
#define CP_WAIT1()  asm volatile("cp.async.wait_group 1;" ::: "memory")

#define QSCALE 0.09016844005556021f   // log2(e)/16
#define SQ     264                     // flash smem row pitch (halves)
#define PP     72                      // P smem pitch (halves), 144B = 9*16
#define ONESH2 0x3C003C00u             // f16x2 {1,1}

// ---------------------------------------------------------------------------
__global__ __launch_bounds__(256) void convert_x(
    const float* __restrict__ x, __half* __restrict__ xh)
{
    size_t i = (size_t)blockIdx.x * 256 + threadIdx.x;
    float4 v = *(const float4*)(x + i * 4);
    *(__half2*)(xh + i * 4)     = __floats2half2_rn(v.x, v.y);
    *(__half2*)(xh + i * 4 + 2) = __floats2half2_rn(v.z, v.w);
}

__global__ __launch_bounds__(256) void wtrans4(
    const float* __restrict__ W0, const float* __restrict__ W1,
    const float* __restrict__ W2, const float* __restrict__ W3,
    __half* __restrict__ Wt)
{
    const float* W = (blockIdx.z == 0) ? W0 : (blockIdx.z == 1) ? W1
                   : (blockIdx.z == 2) ? W2 : W3;
    __half* dst = Wt + (size_t)blockIdx.z * 65536;
    __shared__ float t[32][33];
    const int tx = threadIdx.x & 31, ty = threadIdx.x >> 5;
    const int n0 = blockIdx.x * 32, k0 = blockIdx.y * 32;
#pragma unroll
    for (int j = 0; j < 4; j++)
        t[ty + j * 8][tx] = W[(size_t)(k0 + ty + j * 8) * 256 + n0 + tx];
    __syncthreads();
#pragma unroll
    for (int j = 0; j < 4; j++)
        dst[(size_t)(n0 + ty + j * 8) * 256 + k0 + tx] =
            __float2half(t[tx][ty + j * 8]);
}

// ---------------------------------------------------------------------------
// k-pipelined HMMA GEMM (unchanged from R13).
// ---------------------------------------------------------------------------
#define KC        64
#define SQK       72
#define HA_BYTES  (128 * SQK * 2)
#define HB_BYTES  (128 * SQK * 2)
#define HG2_SMEM  (2 * HA_BYTES + 2 * HB_BYTES)   // 73728

template<int OM>
__global__ __launch_bounds__(256, 2) void hgemm2(
    const __half* __restrict__ A, const __half* __restrict__ BtBase,
    const float* __restrict__ bias0, const float* __restrict__ bias1,
    const float* __restrict__ bias2,
    __half* __restrict__ d0, __half* __restrict__ d1, __half* __restrict__ d2,
    const float* __restrict__ cv, float* __restrict__ wout)
{
    extern __shared__ __align__(16) __half hsm[];
    const uint32_t sb = smem_u32(hsm);
    const int tid = threadIdx.x, lane = tid & 31, w = tid >> 5;
    const int bm = blockIdx.x * 128;
    const int ny = blockIdx.y;
    const int n0 = ny * 128;
    const int z = (OM == 3) ? blockIdx.z : 0;
    const __half* Bt = ((OM == 3) ? BtBase + (size_t)z * 65536 : BtBase) +
                       (size_t)n0 * 256;
    const float* bias = (OM == 3) ? (z == 0 ? bias0 : z == 1 ? bias1 : bias2)
                                  : bias0;
    const __half* ag = A + (size_t)bm * 256;

    auto loadchunk = [&](int ki, int buf) {
        const uint32_t ab = sb + buf * HA_BYTES;
        const uint32_t bb = sb + 2 * HA_BYTES + buf * HB_BYTES;
        const int k0 = ki * KC;
#pragma unroll
        for (int i = 0; i < 4; i++) {
            int c = tid + i * 256, row = c >> 3, co = (c & 7) * 8;
            CP16(ab + (row * SQK + co) * 2, ag + (size_t)row * 256 + k0 + co);
        }
#pragma unroll
        for (int i = 0; i < 4; i++) {
            int c = tid + i * 256, row = c >> 3, co = (c & 7) * 8;
            CP16(bb + (row * SQK + co) * 2, Bt + (size_t)row * 256 + k0 + co);
        }
    };

    loadchunk(0, 0); CP_COMMIT();
    loadchunk(1, 1); CP_COMMIT();

    const int m0 = w * 16;
    const int aoff = ((m0 + (lane & 15)) * SQK + (lane >> 4) * 8) * 2;
    const int krow = (lane & 7) + ((lane >> 4) << 3);
    const int kcol = ((lane >> 3) & 1) * 8;
    const int boff = (krow * SQK + kcol) * 2;

    float oacc[16][4];
#pragma unroll
    for (int j = 0; j < 16; j++)
#pragma unroll
        for (int r = 0; r < 4; r++) oacc[j][r] = 0.f;

    for (int ki = 0; ki < 4; ki++) {
        CP_WAIT1();
        __syncthreads();
        const int buf = ki & 1;
        const uint32_t ab = sb + buf * HA_BYTES + aoff;
        const uint32_t bb = sb + 2 * HA_BYTES + buf * HB_BYTES + boff;
#pragma unroll
        for (int ks = 0; ks < 4; ks++) {
            uint32_t a0, a1, a2, a3;
            ldsm4(a0, a1, a2, a3, ab + ks * 32);
#pragma unroll
            for (int jn = 0; jn < 8; jn++) {
                uint32_t b0, b1, b2, b3;
                ldsm4(b0, b1, b2, b3, bb + (jn * 16 * SQK) * 2 + ks * 32);
                mma16816(oacc[2 * jn],     a0, a1, a2, a3, b0, b1);
                mma16816(oacc[2 * jn + 1], a0, a1, a2, a3, b2, b3);
            }
        }
        __syncthreads();
        if (ki + 2 < 4) loadchunk(ki + 2, buf);
        CP_COMMIT();
    }

    const int g = lane >> 2, qd = lane & 3;
    const size_t row0 = (size_t)(bm + m0 + g);
    const float scale = (OM == 3 && z == 0) ? QSCALE : 1.0f;
    __half* dst = (OM == 3) ? (z == 0 ? d0 : z == 1 ? d1 : d2) : d0;
    float dot0 = 0.f, dot1 = 0.f;
#pragma unroll
    for (int j = 0; j < 16; j++) {
        const int col = n0 + j * 8 + qd * 2;
        const float b0 = bias[col], b1 = bias[col + 1];
        float v00 = (oacc[j][0] + b0) * scale, v01 = (oacc[j][1] + b1) * scale;
        float v10 = (oacc[j][2] + b0) * scale, v11 = (oacc[j][3] + b1) * scale;
        *(__half2*)(dst + row0 * 256 + col)       = __floats2half2_rn(v00, v01);
        *(__half2*)(dst + (row0 + 8) * 256 + col) = __floats2half2_rn(v10, v11);
        if (OM == 0) {
            const float c0 = cv[col], c1 = cv[col + 1];
            dot0 += v00 * c0 + v01 * c1;
            dot1 += v10 * c0 + v11 * c1;
        }
    }
    if (OM == 0) {
        dot0 += __shfl_xor_sync(0xffffffffu, dot0, 1);
        dot0 += __shfl_xor_sync(0xffffffffu, dot0, 2);
        dot1 += __shfl_xor_sync(0xffffffffu, dot1, 1);
        dot1 += __shfl_xor_sync(0xffffffffu, dot1, 2);
        if (qd == 0) {
            wout[(size_t)ny * NROWS + row0]     = dot0;
            wout[(size_t)ny * NROWS + row0 + 8] = dot1;
        }
    }
}

// ---------------------------------------------------------------------------
// Flash attention, 16 warps (512 threads), 1 CTA/SM.
// Warp pair p = w>>1 owns q-rows m0 = p*16..+15.
//   S phase:  warp computes S for its key half (key0 = (w&1)*32), f16 acc,
//             p = 2^s via ex2.f16x2, stored to P smem [128][PP].
//   PV phase: warp reads full-key P A-frags via ldsm, accumulates its
//             d-half (dh = (w&1)*128) in oacc[16][4] (64 regs); l via ones-MMA.
// ---------------------------------------------------------------------------
#define Q_BYTES  (128 * SQ * 2)              // 67584
#define KVB      (64 * SQ * 2)               // 33792
#define P_BYTES  (128 * PP * 2)              // 18432
#define FL_SMEM  (Q_BYTES + 4 * KVB + P_BYTES)   // 221184

__global__ __launch_bounds__(512, 1) void flash_mma(
    const __half* __restrict__ qh, const __half* __restrict__ kh,
    const __half* __restrict__ vh, __half* __restrict__ ctx)
{
    extern __shared__ __align__(16) __half sm[];
    const uint32_t base = smem_u32(sm);
    const uint32_t qs  = base;
    const uint32_t ks0 = base + Q_BYTES;
    const uint32_t vs0 = base + Q_BYTES + 2 * KVB;
    const uint32_t ps  = base + Q_BYTES + 4 * KVB;

    const int tid = threadIdx.x, lane = tid & 31, w = tid >> 5;
    const int bat = blockIdx.x >> 5, qt = blockIdx.x & 31;
    const __half* qg = qh + ((size_t)(bat * 4096 + qt * 128)) * 256;
    const __half* kg = kh + (size_t)bat * 4096 * 256;
    const __half* vg = vh + (size_t)bat * 4096 * 256;

    // Q: 4096 16B chunks -> 8/thread
#pragma unroll
    for (int i = 0; i < 8; i++) {
        int c = tid + i * 512, row = c >> 5, col8 = (c & 31) * 8;
        CP16(qs + (row * SQ + col8) * 2, qg + row * 256 + col8);
    }
    // KV tile 0: 2048 chunks each -> 4/thread
#pragma unroll
    for (int i = 0; i < 4; i++) {
        int c = tid + i * 512, row = c >> 5, col8 = (c & 31) * 8;
        CP16(ks0 + (row * SQ + col8) * 2, kg + row * 256 + col8);
        CP16(vs0 + (row * SQ + col8) * 2, vg + row * 256 + col8);
    }
    CP_COMMIT();
#pragma unroll
    for (int i = 0; i < 4; i++) {
        int c = tid + i * 512, row = c >> 5, col8 = (c & 31) * 8;
        CP16(ks0 + KVB + (row * SQ + col8) * 2, kg + (64 + row) * 256 + col8);
        CP16(vs0 + KVB + (row * SQ + col8) * 2, vg + (64 + row) * 256 + col8);
    }
    CP_COMMIT();

    const int m0 = (w >> 1) * 16;      // q-row block of the pair
    const int key0 = (w & 1) * 32;     // key half for S phase
    const int dh = (w & 1) * 128;      // d half for PV phase
    const int g = lane >> 2, qd = lane & 3;

    float oacc[16][4];
#pragma unroll
    for (int j = 0; j < 16; j++)
#pragma unroll
        for (int r = 0; r < 4; r++) oacc[j][r] = 0.f;
    float lacc[4] = {0.f, 0.f, 0.f, 0.f};

    const uint32_t a_base = qs + ((m0 + (lane & 15)) * SQ + (lane >> 4) * 8) * 2;
    const int krow = (lane & 7) + ((lane >> 4) << 3);
    const int kcol = ((lane >> 3) & 1) * 8;
    const int vrow = (lane & 7) + (((lane >> 3) & 1) << 3);
    const int vcol = (lane >> 4) << 3;
    const uint32_t pa_base = ps + ((m0 + (lane & 15)) * PP + (lane >> 4) * 8) * 2;
    const uint32_t pw_base = ps + ((m0 + g) * PP + key0 + qd * 2) * 2;

    for (int t = 0; t < 64; t++) {
        CP_WAIT1();
        __syncthreads();   // KV ready; previous tile's P fully consumed
        const int bb = t & 1;
        const uint32_t kb_lane = ks0 + bb * KVB +
                                 ((key0 + krow) * SQ + kcol) * 2;
        const uint32_t vb_lane = vs0 + bb * KVB +
                                 (vrow * SQ + dh + vcol) * 2;

        // ---- S = Q @ K^T for this warp's 32-key half (f16 acc) ----
        uint32_t sacc[4][2];
#pragma unroll
        for (int j = 0; j < 4; j++) { sacc[j][0] = 0u; sacc[j][1] = 0u; }
#pragma unroll
        for (int ks = 0; ks < 16; ks++) {
            uint32_t a0, a1, a2, a3;
            ldsm4(a0, a1, a2, a3, a_base + ks * 32);
#pragma unroll
            for (int jn = 0; jn < 2; jn++) {
                uint32_t b0, b1, b2, b3;
                ldsm4(b0, b1, b2, b3,
                      kb_lane + (jn * 16 * SQ) * 2 + ks * 32);
                mma16816h(sacc[2 * jn][0], sacc[2 * jn][1],
                          a0, a1, a2, a3, b0, b1);
                mma16816h(sacc[2 * jn + 1][0], sacc[2 * jn + 1][1],
                          a0, a1, a2, a3, b2, b3);
            }
        }

        // ---- p = 2^s; store P to smem (fp16, C-fragment layout) ----
#pragma unroll
        for (int j = 0; j < 4; j++) {
            sts32(pw_base + j * 16,                  ex2h2(sacc[j][0]));
            sts32(pw_base + 8 * PP * 2 + j * 16,     ex2h2(sacc[j][1]));
        }
        __syncthreads();   // P complete for all warps

        // ---- PV: O += P(full keys) @ V(d-half); l via ones-MMA ----
#pragma unroll
        for (int kk = 0; kk < 4; kk++) {
            uint32_t p0, p1, p2, p3;
            ldsm4(p0, p1, p2, p3, pa_base + kk * 32);
            mma16816(lacc, p0, p1, p2, p3, ONESH2, ONESH2);
#pragma unroll
            for (int dn = 0; dn < 8; dn++) {
                uint32_t b0, b1, b2, b3;
                ldsm4t(b0, b1, b2, b3,
                       vb_lane + ((kk * 16) * SQ + dn * 16) * 2);
                mma16816(oacc[2 * dn],     p0, p1, p2, p3, b0, b1);
                mma16816(oacc[2 * dn + 1], p0, p1, p2, p3, b2, b3);
            }
        }

        __syncthreads();   // PV reads done before next KV load overwrites
        if (t + 2 < 64) {
            const __half* kg2 = kg + (size_t)(t + 2) * 64 * 256;
            const __half* vg2 = vg + (size_t)(t + 2) * 64 * 256;
            const uint32_t kbuf = ks0 + bb * KVB, vbuf = vs0 + bb * KVB;
#pragma unroll
            for (int i = 0; i < 4; i++) {
                int c = tid + i * 512, row = c >> 5, col8 = (c & 31) * 8;
                CP16(kbuf + (row * SQ + col8) * 2, kg2 + row * 256 + col8);
                CP16(vbuf + (row * SQ + col8) * 2, vg2 + row * 256 + col8);
            }
        }
        CP_COMMIT();
    }

    // lacc[0] = row g sum, lacc[2] = row g+8 sum (cols duplicated).
    const float i0 = 1.0f / lacc[0], i1 = 1.0f / lacc[2];

    const size_t row0 = (size_t)(bat * 4096 + qt * 128 + m0 + g);
    __half* o0 = ctx + row0 * 256 + dh + qd * 2;
    __half* o1 = o0 + 8 * 256;
#pragma unroll
    for (int j = 0; j < 16; j++) {
        *(__half2*)(o0 + j * 8) = __floats2half2_rn(oacc[j][0] * i0, oacc[j][1] * i0);
        *(__half2*)(o1 + j * 8) = __floats2half2_rn(oacc[j][2] * i1, oacc[j][3] * i1);
    }
}

// ---------------------------------------------------------------------------
// Pooling: sum the two n-half partials, softmax over sequence, write g_wn.
// ---------------------------------------------------------------------------
__global__ __launch_bounds__(256) void pool_softmax(
    const float* __restrict__ w2, float* __restrict__ wn)
{
    __shared__ float red[8];
    int t = threadIdx.x;
    int warp = t >> 5, lane = t & 31;
    const int b0 = blockIdx.x * 4096;
    float vals[16];
    float mx = -1e30f;
#pragma unroll
    for (int i = 0; i < 16; i++) {
        int r = b0 + t + i * 256;
        vals[i] = w2[r] + w2[NROWS + r];
        mx = fmaxf(mx, vals[i]);
    }
#pragma unroll
    for (int m = 16; m; m >>= 1) mx = fmaxf(mx, __shfl_xor_sync(0xffffffffu, mx, m));
    if (lane == 0) red[warp] = mx;
    __syncthreads();
    float M = red[0];
#pragma unroll
    for (int i = 1; i < 8; i++) M = fmaxf(M, red[i]);
    __syncthreads();
    float s = 0.f;
#pragma unroll
    for (int i = 0; i < 16; i++) { vals[i] = __expf(vals[i] - M); s += vals[i]; }
#pragma unroll
    for (int m = 16; m; m >>= 1) s += __shfl_xor_sync(0xffffffffu, s, m);
    if (lane == 0) red[warp] = s;
    __syncthreads();
    float S = 0.f;
#pragma unroll
    for (int i = 0; i < 8; i++) S += red[i];
    float inv = 1.0f / S;
#pragma unroll
    for (int i = 0; i < 16; i++) wn[b0 + t + i * 256] = vals[i] * inv;
}

// out = fp16(logits) * nw, fp32 result.
__global__ __launch_bounds__(256) void scale_out(
    const __half* __restrict__ hlog, const float* __restrict__ w,
    float* __restrict__ out)
{
    int i = blockIdx.x * 256 + threadIdx.x;
    const __half2 h0 = *(const __half2*)(hlog + (size_t)i * 4);
    const __half2 h1 = *(const __half2*)(hlog + (size_t)i * 4 + 2);
    float2 f0 = __half22float2(h0), f1 = __half22float2(h1);
    float nw = w[i >> 6];
    float4 vv = make_float4(f0.x * nw, f0.y * nw, f1.x * nw, f1.y * nw);
    *(float4*)(out + (size_t)i * 4) = vv;
}

// ---------------------------------------------------------------------------
extern "C" void kernel_launch(void* const* d_in, const int* in_sizes, int n_in,
                              void* d_out, int out_size)
{
    const float* x  = (const float*)d_in[0];
    const float* Wq = (const float*)d_in[1];
    const float* bq = (const float*)d_in[2];
    const float* Wk = (const float*)d_in[3];
    const float* bk = (const float*)d_in[4];
    const float* Wv = (const float*)d_in[5];
    const float* bv = (const float*)d_in[6];
    const float* Wo = (const float*)d_in[7];
    const float* bo = (const float*)d_in[8];
    const float* cv = (const float*)d_in[9];
    float* out = (float*)d_out;

    __half *gxh, *gwt, *gqh, *gkh, *gvh, *gctxh;
    float *gw, *gwn;
    cudaGetSymbolAddress((void**)&gxh,   g_xh);
    cudaGetSymbolAddress((void**)&gwt,   g_wt);
    cudaGetSymbolAddress((void**)&gqh,   g_qh);
    cudaGetSymbolAddress((void**)&gkh,   g_kh);
    cudaGetSymbolAddress((void**)&gvh,   g_vh);
    cudaGetSymbolAddress((void**)&gctxh, g_ctxh);
    cudaGetSymbolAddress((void**)&gw,    g_w);
    cudaGetSymbolAddress((void**)&gwn,   g_wn);

    cudaFuncSetAttribute(flash_mma, cudaFuncAttributeMaxDynamicSharedMemorySize,
                         FL_SMEM);
    cudaFuncSetAttribute(hgemm2<3>, cudaFuncAttributeMaxDynamicSharedMemorySize,
                         HG2_SMEM);
    cudaFuncSetAttribute(hgemm2<0>, cudaFuncAttributeMaxDynamicSharedMemorySize,
                         HG2_SMEM);

    __half* wo_t = gwt + 196608;

    convert_x<<<8192, 256>>>(x, gxh);
    wtrans4<<<dim3(8, 8, 4), 256>>>(Wq, Wk, Wv, Wo, gwt);

    hgemm2<3><<<dim3(256, 2, 3), 256, HG2_SMEM>>>(
        gxh, gwt, bq, bk, bv, gqh, gkh, gvh, nullptr, nullptr);

    flash_mma<<<256, 512, FL_SMEM>>>(gqh, gkh, gvh, gctxh);

    hgemm2<0><<<dim3(256, 2, 1), 256, HG2_SMEM>>>(
        gctxh, wo_t, bo, nullptr, nullptr,
        gxh, nullptr, nullptr, cv, gw);

    pool_softmax<<<8, 256>>>(gw, gwn);
    scale_out<<<8192, 256>>>(gxh, gwn, out);
}

// round 15
// speedup vs baseline: 1.1052x; 1.1052x over previous
#include <cuda_runtime.h>
#include <cuda_fp16.h>
#include <cstdint>

// ---------------------------------------------------------------------------
// VideoAttentionModel  B=8, S=4096, D=256, fp32 in/out.
// Round 15: R13 config (best known) with single-sync flash mainloop:
// tile t+1's KV loads issued right after the data-ready barrier, into the
// buffer whose readers finished at t-1 — removes 64 of 128 barriers.
// ---------------------------------------------------------------------------

#define NROWS 32768
#define NELEM (NROWS * 256)

// Scratch (device globals — allocation-free rule)
__device__ __half g_xh[NELEM];     // x fp16; later reused as fp16 logits
__device__ __half g_wt[4 * 256 * 256];
__device__ __half g_qh[NELEM];
__device__ __half g_kh[NELEM];
__device__ __half g_vh[NELEM];
__device__ __half g_ctxh[NELEM];
__device__ float  g_w[2 * NROWS];
__device__ float  g_wn[NROWS];

// ---------------------------------------------------------------------------
// PTX helpers (sm_80-era instructions only)
// ---------------------------------------------------------------------------
__device__ __forceinline__ uint32_t smem_u32(const void* p) {
    uint32_t a;
    asm("{ .reg .u64 t; cvta.to.shared.u64 t, %1; cvt.u32.u64 %0, t; }"
        : "=r"(a) : "l"(p));
    return a;
}
__device__ __forceinline__ uint32_t ex2h2(uint32_t x) {   // 2^x on f16x2
    uint32_t y; asm("ex2.approx.f16x2 %0, %1;" : "=r"(y) : "r"(x)); return y;
}
__device__ __forceinline__ void ldsm4(uint32_t &r0, uint32_t &r1, uint32_t &r2,
                                      uint32_t &r3, uint32_t a) {
    asm volatile("ldmatrix.sync.aligned.m8n8.x4.shared.b16 {%0,%1,%2,%3}, [%4];"
                 : "=r"(r0), "=r"(r1), "=r"(r2), "=r"(r3) : "r"(a));
}
__device__ __forceinline__ void ldsm4t(uint32_t &r0, uint32_t &r1, uint32_t &r2,
                                       uint32_t &r3, uint32_t a) {
    asm volatile("ldmatrix.sync.aligned.m8n8.x4.trans.shared.b16 {%0,%1,%2,%3}, [%4];"
                 : "=r"(r0), "=r"(r1), "=r"(r2), "=r"(r3) : "r"(a));
}
// fp32-accumulate HMMA
__device__ __forceinline__ void mma16816(float (&c)[4], uint32_t a0, uint32_t a1,
                                         uint32_t a2, uint32_t a3,
                                         uint32_t b0, uint32_t b1) {
    asm volatile(
        "mma.sync.aligned.m16n8k16.row.col.f32.f16.f16.f32 "
        "{%0,%1,%2,%3}, {%4,%5,%6,%7}, {%8,%9}, {%0,%1,%2,%3};"
        : "+f"(c[0]), "+f"(c[1]), "+f"(c[2]), "+f"(c[3])
        : "r"(a0), "r"(a1), "r"(a2), "r"(a3), "r"(b0), "r"(b1));
}
// fp16-accumulate HMMA (scores only)
__device__ __forceinline__ void mma16816h(uint32_t &c0, uint32_t &c1,
                                          uint32_t a0, uint32_t a1,
                                          uint32_t a2, uint32_t a3,
                                          uint32_t b0, uint32_t b1) {
    asm volatile(
        "mma.sync.aligned.m16n8k16.row.col.f16.f16.f16.f16 "
        "{%0,%1}, {%2,%3,%4,%5}, {%6,%7}, {%0,%1};"
        : "+r"(c0), "+r"(c1)
        : "r"(a0), "r"(a1), "r"(a2), "r"(a3), "r"(b0), "r"(b1));
}

#define CP16(s, g) \
    asm volatile("cp.async.cg.shared.global [%0], [%1], 16;" :: "r"(s), "l"(g))
#define CP_COMMIT() asm volatile("cp.async.commit_group;" ::: "memory")
#define CP_WAIT1()  asm volatile("cp.async.wait_group 1;" ::: "memory")
#define CP_WAIT0()  asm volatile("cp.async.wait_group 0;" ::: "memory")

#define QSCALE 0.09016844005556021f   // log2(e)/16
#define SQ     264                     // flash smem row pitch (halves)
#define ONESH2 0x3C003C00u             // f16x2 {1,1}

// ---------------------------------------------------------------------------
__global__ __launch_bounds__(256) void convert_x(
    const float* __restrict__ x, __half* __restrict__ xh)
{
    size_t i = (size_t)blockIdx.x * 256 + threadIdx.x;
    float4 v = *(const float4*)(x + i * 4);
    *(__half2*)(xh + i * 4)     = __floats2half2_rn(v.x, v.y);
    *(__half2*)(xh + i * 4 + 2) = __floats2half2_rn(v.z, v.w);
}

__global__ __launch_bounds__(256) void wtrans4(
    const float* __restrict__ W0, const float* __restrict__ W1,
    const float* __restrict__ W2, const float* __restrict__ W3,
    __half* __restrict__ Wt)
{
    const float* W = (blockIdx.z == 0) ? W0 : (blockIdx.z == 1) ? W1
                   : (blockIdx.z == 2) ? W2 : W3;
    __half* dst = Wt + (size_t)blockIdx.z * 65536;
    __shared__ float t[32][33];
    const int tx = threadIdx.x & 31, ty = threadIdx.x >> 5;
    const int n0 = blockIdx.x * 32, k0 = blockIdx.y * 32;
#pragma unroll
    for (int j = 0; j < 4; j++)
        t[ty + j * 8][tx] = W[(size_t)(k0 + ty + j * 8) * 256 + n0 + tx];
    __syncthreads();
#pragma unroll
    for (int j = 0; j < 4; j++)
        dst[(size_t)(n0 + ty + j * 8) * 256 + k0 + tx] =
            __float2half(t[tx][ty + j * 8]);
}

// ---------------------------------------------------------------------------
// k-pipelined HMMA GEMM (128m x 128n, KC=64, 2 CTAs/SM). Unchanged from R13.
// OM=3: QKV fused fp16 out (z selects weight/bias/dst; Q scaled by QSCALE).
// OM=0: fp16 logits out (d0) + per-n-half pooling dot -> wout.
// ---------------------------------------------------------------------------
#define KC        64
#define SQK       72
#define HA_BYTES  (128 * SQK * 2)
#define HB_BYTES  (128 * SQK * 2)
#define HG2_SMEM  (2 * HA_BYTES + 2 * HB_BYTES)   // 73728

template<int OM>
__global__ __launch_bounds__(256, 2) void hgemm2(
    const __half* __restrict__ A, const __half* __restrict__ BtBase,
    const float* __restrict__ bias0, const float* __restrict__ bias1,
    const float* __restrict__ bias2,
    __half* __restrict__ d0, __half* __restrict__ d1, __half* __restrict__ d2,
    const float* __restrict__ cv, float* __restrict__ wout)
{
    extern __shared__ __align__(16) __half hsm[];
    const uint32_t sb = smem_u32(hsm);
    const int tid = threadIdx.x, lane = tid & 31, w = tid >> 5;
    const int bm = blockIdx.x * 128;
    const int ny = blockIdx.y;
    const int n0 = ny * 128;
    const int z = (OM == 3) ? blockIdx.z : 0;
    const __half* Bt = ((OM == 3) ? BtBase + (size_t)z * 65536 : BtBase) +
                       (size_t)n0 * 256;
    const float* bias = (OM == 3) ? (z == 0 ? bias0 : z == 1 ? bias1 : bias2)
                                  : bias0;
    const __half* ag = A + (size_t)bm * 256;

    auto loadchunk = [&](int ki, int buf) {
        const uint32_t ab = sb + buf * HA_BYTES;
        const uint32_t bb = sb + 2 * HA_BYTES + buf * HB_BYTES;
        const int k0 = ki * KC;
#pragma unroll
        for (int i = 0; i < 4; i++) {
            int c = tid + i * 256, row = c >> 3, co = (c & 7) * 8;
            CP16(ab + (row * SQK + co) * 2, ag + (size_t)row * 256 + k0 + co);
        }
#pragma unroll
        for (int i = 0; i < 4; i++) {
            int c = tid + i * 256, row = c >> 3, co = (c & 7) * 8;
            CP16(bb + (row * SQK + co) * 2, Bt + (size_t)row * 256 + k0 + co);
        }
    };

    loadchunk(0, 0); CP_COMMIT();
    loadchunk(1, 1); CP_COMMIT();

    const int m0 = w * 16;
    const int aoff = ((m0 + (lane & 15)) * SQK + (lane >> 4) * 8) * 2;
    const int krow = (lane & 7) + ((lane >> 4) << 3);
    const int kcol = ((lane >> 3) & 1) * 8;
    const int boff = (krow * SQK + kcol) * 2;

    float oacc[16][4];
#pragma unroll
    for (int j = 0; j < 16; j++)
#pragma unroll
        for (int r = 0; r < 4; r++) oacc[j][r] = 0.f;

    for (int ki = 0; ki < 4; ki++) {
        CP_WAIT1();
        __syncthreads();
        const int buf = ki & 1;
        const uint32_t ab = sb + buf * HA_BYTES + aoff;
        const uint32_t bb = sb + 2 * HA_BYTES + buf * HB_BYTES + boff;
#pragma unroll
        for (int ks = 0; ks < 4; ks++) {
            uint32_t a0, a1, a2, a3;
            ldsm4(a0, a1, a2, a3, ab + ks * 32);
#pragma unroll
            for (int jn = 0; jn < 8; jn++) {
                uint32_t b0, b1, b2, b3;
                ldsm4(b0, b1, b2, b3, bb + (jn * 16 * SQK) * 2 + ks * 32);
                mma16816(oacc[2 * jn],     a0, a1, a2, a3, b0, b1);
                mma16816(oacc[2 * jn + 1], a0, a1, a2, a3, b2, b3);
            }
        }
        __syncthreads();
        if (ki + 2 < 4) loadchunk(ki + 2, buf);
        CP_COMMIT();
    }

    const int g = lane >> 2, qd = lane & 3;
    const size_t row0 = (size_t)(bm + m0 + g);
    const float scale = (OM == 3 && z == 0) ? QSCALE : 1.0f;
    __half* dst = (OM == 3) ? (z == 0 ? d0 : z == 1 ? d1 : d2) : d0;
    float dot0 = 0.f, dot1 = 0.f;
#pragma unroll
    for (int j = 0; j < 16; j++) {
        const int col = n0 + j * 8 + qd * 2;
        const float b0 = bias[col], b1 = bias[col + 1];
        float v00 = (oacc[j][0] + b0) * scale, v01 = (oacc[j][1] + b1) * scale;
        float v10 = (oacc[j][2] + b0) * scale, v11 = (oacc[j][3] + b1) * scale;
        *(__half2*)(dst + row0 * 256 + col)       = __floats2half2_rn(v00, v01);
        *(__half2*)(dst + (row0 + 8) * 256 + col) = __floats2half2_rn(v10, v11);
        if (OM == 0) {
            const float c0 = cv[col], c1 = cv[col + 1];
            dot0 += v00 * c0 + v01 * c1;
            dot1 += v10 * c0 + v11 * c1;
        }
    }
    if (OM == 0) {
        dot0 += __shfl_xor_sync(0xffffffffu, dot0, 1);
        dot0 += __shfl_xor_sync(0xffffffffu, dot0, 2);
        dot1 += __shfl_xor_sync(0xffffffffu, dot1, 1);
        dot1 += __shfl_xor_sync(0xffffffffu, dot1, 2);
        if (qd == 0) {
            wout[(size_t)ny * NROWS + row0]     = dot0;
            wout[(size_t)ny * NROWS + row0 + 8] = dot1;
        }
    }
}

// ---------------------------------------------------------------------------
// Flash attention: 128 q rows/CTA, 8 warps, 64-key tiles, double-buffered KV.
// SINGLE sync per tile: loads for t+1 issued right after the data-ready
// barrier into buffer (t+1)&1 (its readers finished at tile t-1, which the
// barrier orders). wait_group 0 is reached one full tile after commit.
// ---------------------------------------------------------------------------
#define Q_BYTES  (128 * SQ * 2)
#define KV_BYTES (64 * SQ * 2)
#define FL_SMEM  (Q_BYTES + 4 * KV_BYTES)   // 202752 B

__global__ __launch_bounds__(256, 1) void flash_mma(
    const __half* __restrict__ qh, const __half* __restrict__ kh,
    const __half* __restrict__ vh, __half* __restrict__ ctx)
{
    extern __shared__ __align__(16) __half sm[];
    const uint32_t base = smem_u32(sm);
    const uint32_t qs = base;
    const uint32_t ks0 = base + Q_BYTES;
    const uint32_t vs0 = base + Q_BYTES + 2 * KV_BYTES;

    const int tid = threadIdx.x, lane = tid & 31, w = tid >> 5;
    const int bat = blockIdx.x >> 5, qt = blockIdx.x & 31;
    const __half* qg = qh + ((size_t)(bat * 4096 + qt * 128)) * 256;
    const __half* kg = kh + (size_t)bat * 4096 * 256;
    const __half* vg = vh + (size_t)bat * 4096 * 256;

    // Q + KV tile 0 in one group.
#pragma unroll
    for (int i = 0; i < 16; i++) {
        int c = tid + i * 256, row = c >> 5, col8 = (c & 31) * 8;
        CP16(qs + (row * SQ + col8) * 2, qg + row * 256 + col8);
    }
#pragma unroll
    for (int i = 0; i < 8; i++) {
        int c = tid + i * 256, row = c >> 5, col8 = (c & 31) * 8;
        CP16(ks0 + (row * SQ + col8) * 2, kg + row * 256 + col8);
        CP16(vs0 + (row * SQ + col8) * 2, vg + row * 256 + col8);
    }
    CP_COMMIT();

    const int m0 = w * 16;
    const int g = lane >> 2, qd = lane & 3;

    float oacc[32][4];
#pragma unroll
    for (int j = 0; j < 32; j++)
#pragma unroll
        for (int r = 0; r < 4; r++) oacc[j][r] = 0.f;
    float lacc[4] = {0.f, 0.f, 0.f, 0.f};

    const uint32_t a_base = qs + ((m0 + (lane & 15)) * SQ + (lane >> 4) * 8) * 2;
    const int krow = (lane & 7) + ((lane >> 4) << 3);
    const int kcol = ((lane >> 3) & 1) * 8;
    const int vrow = (lane & 7) + (((lane >> 3) & 1) << 3);
    const int vcol = (lane >> 4) << 3;

    for (int t = 0; t < 64; t++) {
        const int bb = t & 1;
        CP_WAIT0();        // tile t's data complete (committed >= 1 tile ago)
        __syncthreads();   // (a) data visible to all warps
                           // (b) all warps past tile t-1 -> buffer (t+1)&1 free
        if (t + 1 < 64) {
            const __half* kg2 = kg + (size_t)(t + 1) * 64 * 256;
            const __half* vg2 = vg + (size_t)(t + 1) * 64 * 256;
            const uint32_t kbuf = ks0 + ((t + 1) & 1) * KV_BYTES;
            const uint32_t vbuf = vs0 + ((t + 1) & 1) * KV_BYTES;
#pragma unroll
            for (int i = 0; i < 8; i++) {
                int c = tid + i * 256, row = c >> 5, col8 = (c & 31) * 8;
                CP16(kbuf + (row * SQ + col8) * 2, kg2 + row * 256 + col8);
                CP16(vbuf + (row * SQ + col8) * 2, vg2 + row * 256 + col8);
            }
            CP_COMMIT();
        }

        const uint32_t kb_lane = ks0 + bb * KV_BYTES + (krow * SQ + kcol) * 2;
        const uint32_t vb_lane = vs0 + bb * KV_BYTES + (vrow * SQ + vcol) * 2;

        // ---- S = Q @ K^T (f16 acc, 1-deep fragment prefetch) ----
        uint32_t sacc[8][2];
#pragma unroll
        for (int j = 0; j < 8; j++) { sacc[j][0] = 0u; sacc[j][1] = 0u; }

        uint32_t af[2][4], bf[2][4][4];
        ldsm4(af[0][0], af[0][1], af[0][2], af[0][3], a_base);
#pragma unroll
        for (int jn = 0; jn < 4; jn++)
            ldsm4(bf[0][jn][0], bf[0][jn][1], bf[0][jn][2], bf[0][jn][3],
                  kb_lane + (jn * 16 * SQ) * 2);
#pragma unroll
        for (int ks = 0; ks < 16; ks++) {
            const int cu = ks & 1, nx = cu ^ 1;
            if (ks < 15) {
                ldsm4(af[nx][0], af[nx][1], af[nx][2], af[nx][3],
                      a_base + (ks + 1) * 32);
#pragma unroll
                for (int jn = 0; jn < 4; jn++)
                    ldsm4(bf[nx][jn][0], bf[nx][jn][1], bf[nx][jn][2],
                          bf[nx][jn][3],
                          kb_lane + (jn * 16 * SQ) * 2 + (ks + 1) * 32);
            }
#pragma unroll
            for (int jn = 0; jn < 4; jn++) {
                mma16816h(sacc[2 * jn][0], sacc[2 * jn][1],
                          af[cu][0], af[cu][1], af[cu][2], af[cu][3],
                          bf[cu][jn][0], bf[cu][jn][1]);
                mma16816h(sacc[2 * jn + 1][0], sacc[2 * jn + 1][1],
                          af[cu][0], af[cu][1], af[cu][2], af[cu][3],
                          bf[cu][jn][2], bf[cu][jn][3]);
            }
        }

        // ---- prefetch first V fragment (overlaps softmax) ----
        uint32_t vf[2][4];
        ldsm4t(vf[0][0], vf[0][1], vf[0][2], vf[0][3], vb_lane);

        // ---- softmax: p = 2^s directly on f16x2 fragments ----
        uint32_t ph[8][2];
#pragma unroll
        for (int j = 0; j < 8; j++) {
            ph[j][0] = ex2h2(sacc[j][0]);
            ph[j][1] = ex2h2(sacc[j][1]);
        }
        // row sums: lacc += P @ ones (fp32 acc, persistent across tiles)
#pragma unroll
        for (int kk = 0; kk < 4; kk++)
            mma16816(lacc, ph[2 * kk][0], ph[2 * kk][1],
                     ph[2 * kk + 1][0], ph[2 * kk + 1][1], ONESH2, ONESH2);

        // ---- O += P @ V (fp32 acc, flattened loop, 1-deep V prefetch) ----
#pragma unroll
        for (int idx = 0; idx < 64; idx++) {
            const int cu = idx & 1, nx = cu ^ 1;
            const int kk = idx >> 4, dn = idx & 15;
            if (idx < 63) {
                const int kk2 = (idx + 1) >> 4, dn2 = (idx + 1) & 15;
                ldsm4t(vf[nx][0], vf[nx][1], vf[nx][2], vf[nx][3],
                       vb_lane + ((kk2 * 16) * SQ + dn2 * 16) * 2);
            }
            mma16816(oacc[2 * dn],
                     ph[2 * kk][0], ph[2 * kk][1],
                     ph[2 * kk + 1][0], ph[2 * kk + 1][1],
                     vf[cu][0], vf[cu][1]);
            mma16816(oacc[2 * dn + 1],
                     ph[2 * kk][0], ph[2 * kk][1],
                     ph[2 * kk + 1][0], ph[2 * kk + 1][1],
                     vf[cu][2], vf[cu][3]);
        }
    }

    const float i0 = 1.0f / lacc[0], i1 = 1.0f / lacc[2];

    const size_t row0 = (size_t)(bat * 4096 + qt * 128 + m0 + g);
    __half* o0 = ctx + row0 * 256 + qd * 2;
    __half* o1 = o0 + 8 * 256;
#pragma unroll
    for (int j = 0; j < 32; j++) {
        *(__half2*)(o0 + j * 8) = __floats2half2_rn(oacc[j][0] * i0, oacc[j][1] * i0);
        *(__half2*)(o1 + j * 8) = __floats2half2_rn(oacc[j][2] * i1, oacc[j][3] * i1);
    }
}

// ---------------------------------------------------------------------------
// Pooling: sum the two n-half partials, softmax over sequence, write g_wn.
// ---------------------------------------------------------------------------
__global__ __launch_bounds__(256) void pool_softmax(
    const float* __restrict__ w2, float* __restrict__ wn)
{
    __shared__ float red[8];
    int t = threadIdx.x;
    int warp = t >> 5, lane = t & 31;
    const int b0 = blockIdx.x * 4096;
    float vals[16];
    float mx = -1e30f;
#pragma unroll
    for (int i = 0; i < 16; i++) {
        int r = b0 + t + i * 256;
        vals[i] = w2[r] + w2[NROWS + r];
        mx = fmaxf(mx, vals[i]);
    }
#pragma unroll
    for (int m = 16; m; m >>= 1) mx = fmaxf(mx, __shfl_xor_sync(0xffffffffu, mx, m));
    if (lane == 0) red[warp] = mx;
    __syncthreads();
    float M = red[0];
#pragma unroll
    for (int i = 1; i < 8; i++) M = fmaxf(M, red[i]);
    __syncthreads();
    float s = 0.f;
#pragma unroll
    for (int i = 0; i < 16; i++) { vals[i] = __expf(vals[i] - M); s += vals[i]; }
#pragma unroll
    for (int m = 16; m; m >>= 1) s += __shfl_xor_sync(0xffffffffu, s, m);
    if (lane == 0) red[warp] = s;
    __syncthreads();
    float S = 0.f;
#pragma unroll
    for (int i = 0; i < 8; i++) S += red[i];
    float inv = 1.0f / S;
#pragma unroll
    for (int i = 0; i < 16; i++) wn[b0 + t + i * 256] = vals[i] * inv;
}

// out = fp16(logits) * nw, fp32 result.
__global__ __launch_bounds__(256) void scale_out(
    const __half* __restrict__ hlog, const float* __restrict__ w,
    float* __restrict__ out)
{
    int i = blockIdx.x * 256 + threadIdx.x;
    const __half2 h0 = *(const __half2*)(hlog + (size_t)i * 4);
    const __half2 h1 = *(const __half2*)(hlog + (size_t)i * 4 + 2);
    float2 f0 = __half22float2(h0), f1 = __half22float2(h1);
    float nw = w[i >> 6];
    float4 vv = make_float4(f0.x * nw, f0.y * nw, f1.x * nw, f1.y * nw);
    *(float4*)(out + (size_t)i * 4) = vv;
}

// ---------------------------------------------------------------------------
extern "C" void kernel_launch(void* const* d_in, const int* in_sizes, int n_in,
                              void* d_out, int out_size)
{
    const float* x  = (const float*)d_in[0];
    const float* Wq = (const float*)d_in[1];
    const float* bq = (const float*)d_in[2];
    const float* Wk = (const float*)d_in[3];
    const float* bk = (const float*)d_in[4];
    const float* Wv = (const float*)d_in[5];
    const float* bv = (const float*)d_in[6];
    const float* Wo = (const float*)d_in[7];
    const float* bo = (const float*)d_in[8];
    const float* cv = (const float*)d_in[9];
    float* out = (float*)d_out;

    __half *gxh, *gwt, *gqh, *gkh, *gvh, *gctxh;
    float *gw, *gwn;
    cudaGetSymbolAddress((void**)&gxh,   g_xh);
    cudaGetSymbolAddress((void**)&gwt,   g_wt);
    cudaGetSymbolAddress((void**)&gqh,   g_qh);
    cudaGetSymbolAddress((void**)&gkh,   g_kh);
    cudaGetSymbolAddress((void**)&gvh,   g_vh);
    cudaGetSymbolAddress((void**)&gctxh, g_ctxh);
    cudaGetSymbolAddress((void**)&gw,    g_w);
    cudaGetSymbolAddress((void**)&gwn,   g_wn);

    cudaFuncSetAttribute(flash_mma, cudaFuncAttributeMaxDynamicSharedMemorySize,
                         FL_SMEM);
    cudaFuncSetAttribute(hgemm2<3>, cudaFuncAttributeMaxDynamicSharedMemorySize,
                         HG2_SMEM);
    cudaFuncSetAttribute(hgemm2<0>, cudaFuncAttributeMaxDynamicSharedMemorySize,
                         HG2_SMEM);

    __half* wo_t = gwt + 196608;

    convert_x<<<8192, 256>>>(x, gxh);
    wtrans4<<<dim3(8, 8, 4), 256>>>(Wq, Wk, Wv, Wo, gwt);

    hgemm2<3><<<dim3(256, 2, 3), 256, HG2_SMEM>>>(
        gxh, gwt, bq, bk, bv, gqh, gkh, gvh, nullptr, nullptr);

    flash_mma<<<256, 256, FL_SMEM>>>(gqh, gkh, gvh, gctxh);

    hgemm2<0><<<dim3(256, 2, 1), 256, HG2_SMEM>>>(
        gctxh, wo_t, bo, nullptr, nullptr,
        gxh, nullptr, nullptr, cv, gw);

    pool_softmax<<<8, 256>>>(gw, gwn);
    scale_out<<<8192, 256>>>(gxh, gwn, out);
}